// round 3
// baseline (speedup 1.0000x reference)
#include <cuda_runtime.h>
#include <math.h>

// ---------------------------------------------------------------------------
// mLSTM cell, B=128, D_IN=1024, H=1024
// inputs (resolved BY SIZE at launch, order-agnostic):
//   x [128,1024], C [128,1024,1024], n [128,1024], h [128,1024] (dead),
//   W_proj [1024,4096], b_proj [4096], W_gates [1024,3072], b_gates [3072]
// output: concat[ h_new (128*1024), C_new (128*1024*1024), n_new (128*1024) ]
//
// NOTE: scratch lives in __device__ globals and is ONLY referenced from
// device code (passing a __device__ symbol as a host-side kernel arg is
// invalid and was the round-1/2 bug).
// ---------------------------------------------------------------------------

#define Bsz   128
#define Hdim  1024
#define NQKV  3072   // we skip the dead 'g' quarter of proj

__device__ float g_qkv[Bsz * NQKV];     // [b][ q(0:1024) k(1024:2048) v(2048:3072) ]
__device__ float g_ifo[Bsz * NQKV];     // [b][ i f o ]
__device__ float g_hpart[2 * Bsz * Hdim];
__device__ float g_denom[Bsz];

// ---------------------------------------------------------------------------
// GEMM: out[M=128, N=3072] = act(A[128,K=1024] * W[1024,N] + bias)
// MODE 0 (proj):  A = x (arg), ldw = 4096, out = g_qkv, tanh for n<2048
// MODE 1 (gates): A = g_qkv v-slice, ldw = 3072, out = g_ifo, sigmoid
// Tiles: BM=64 BN=64 BK=16, 128 threads, 4x8 per-thread register tile.
// ---------------------------------------------------------------------------
template <int MODE>
__global__ __launch_bounds__(128) void gemm_act_kernel(
    const float* __restrict__ Aext,
    const float* __restrict__ W,
    const float* __restrict__ bias)
{
    constexpr int BM = 64, BN = 64, BK = 16;
    const float* __restrict__ A = (MODE == 0) ? Aext : (const float*)(g_qkv + 2048);
    const int lda = (MODE == 0) ? 1024 : NQKV;
    const int ldw = (MODE == 0) ? 4096 : 3072;
    float* __restrict__ out = (MODE == 0) ? g_qkv : g_ifo;

    __shared__ float As[BK][BM + 1];   // transposed, padded
    __shared__ float Ws[BK][BN];

    const int tid = threadIdx.x;
    const int bm = blockIdx.y * BM;
    const int bn = blockIdx.x * BN;

    const int aRow = tid >> 2;         // 0..31 (and +32)
    const int aK4  = (tid & 3) * 4;
    const int wRow = tid >> 4;         // 0..7 (and +8)
    const int wN4  = (tid & 15) * 4;

    const int trow = (tid >> 3) * 4;   // 0..60 step 4
    const int tcol = (tid & 7) * 8;    // 0..56 step 8

    float acc[4][8];
#pragma unroll
    for (int r = 0; r < 4; r++)
#pragma unroll
        for (int c = 0; c < 8; c++) acc[r][c] = 0.f;

    for (int k0 = 0; k0 < 1024; k0 += BK) {
#pragma unroll
        for (int rr = 0; rr < 2; rr++) {
            int row = aRow + rr * 32;
            float4 av = *(const float4*)(A + (size_t)(bm + row) * lda + k0 + aK4);
            As[aK4 + 0][row] = av.x;
            As[aK4 + 1][row] = av.y;
            As[aK4 + 2][row] = av.z;
            As[aK4 + 3][row] = av.w;
        }
#pragma unroll
        for (int rr = 0; rr < 2; rr++) {
            int krow = wRow + rr * 8;
            *(float4*)&Ws[krow][wN4] =
                *(const float4*)(W + (size_t)(k0 + krow) * ldw + bn + wN4);
        }
        __syncthreads();

#pragma unroll
        for (int kk = 0; kk < BK; kk++) {
            float a[4], wv[8];
#pragma unroll
            for (int r = 0; r < 4; r++) a[r] = As[kk][trow + r];
#pragma unroll
            for (int c = 0; c < 8; c++) wv[c] = Ws[kk][tcol + c];
#pragma unroll
            for (int r = 0; r < 4; r++)
#pragma unroll
                for (int c = 0; c < 8; c++)
                    acc[r][c] = fmaf(a[r], wv[c], acc[r][c]);
        }
        __syncthreads();
    }

#pragma unroll
    for (int r = 0; r < 4; r++) {
        int m = bm + trow + r;
#pragma unroll
        for (int c = 0; c < 8; c++) {
            int nn = bn + tcol + c;
            float v = acc[r][c] + bias[nn];
            if (MODE == 0) {
                if (nn < 2048) v = tanhf(v);     // q, k; v-quarter identity
            } else {
                v = 1.0f / (1.0f + expf(-v));    // sigmoid
            }
            out[(size_t)m * NQKV + nn] = v;
        }
    }
}

// ---------------------------------------------------------------------------
// K2b: n_new = f*n + i*k ; denom[b] = max(sum_d q*n_new, 1e-6)
// ---------------------------------------------------------------------------
__global__ __launch_bounds__(256) void nnew_denom_kernel(
    const float* __restrict__ n_in, float* __restrict__ out_n)
{
    const int b = blockIdx.x;
    const int tid = threadIdx.x;
    __shared__ float red[256];

    float psum = 0.f;
#pragma unroll
    for (int d = tid; d < Hdim; d += 256) {
        float iv = g_ifo[b * NQKV + d];
        float fv = g_ifo[b * NQKV + 1024 + d];
        float kv = g_qkv[b * NQKV + 1024 + d];
        float qv = g_qkv[b * NQKV + d];
        float nn = fv * n_in[b * Hdim + d] + iv * kv;
        out_n[b * Hdim + d] = nn;
        psum += qv * nn;
    }
    red[tid] = psum;
    __syncthreads();
#pragma unroll
    for (int s = 128; s > 0; s >>= 1) {
        if (tid < s) red[tid] += red[tid + s];
        __syncthreads();
    }
    if (tid == 0) g_denom[b] = fmaxf(red[0], 1e-6f);
}

// ---------------------------------------------------------------------------
// K3: streaming C update fused with h_lin reduction (single pass over C).
//   C_new[b,h,d] = f[b,h]*C[b,h,d] + (i[b,h]*k[b,h]) * v[b,d]
//   h_lin_part[ht][b,d] = sum_{h in tile} q[b,h]*C_new[b,h,d]
// grid = 128 b * 2 htiles * 2 dtiles = 512 blocks, 128 threads, float4/thread
// ---------------------------------------------------------------------------
#define TILE_H 512
#define TILE_D 512

__global__ __launch_bounds__(128) void update_C_kernel(
    const float* __restrict__ C, float* __restrict__ outC)
{
    const int bid = blockIdx.x;
    const int b  = bid >> 2;
    const int ht = (bid >> 1) & 1;
    const int dt = bid & 1;
    const int tid = threadIdx.x;

    __shared__ float qs[TILE_H], fs[TILE_H], iks[TILE_H];
    for (int j = tid; j < TILE_H; j += 128) {
        int h = ht * TILE_H + j;
        qs[j]  = g_qkv[b * NQKV + h];
        float kv = g_qkv[b * NQKV + 1024 + h];
        float iv = g_ifo[b * NQKV + h];
        fs[j]  = g_ifo[b * NQKV + 1024 + h];
        iks[j] = iv * kv;
    }
    __syncthreads();

    const int d = dt * TILE_D + tid * 4;
    const float4 v4 = *(const float4*)(g_qkv + b * NQKV + 2048 + d);

    const size_t base = (size_t)b * Hdim * Hdim + (size_t)ht * TILE_H * Hdim + d;
    const float* __restrict__ src = C + base;
    float* __restrict__ dst = outC + base;

    float4 acc = make_float4(0.f, 0.f, 0.f, 0.f);

#pragma unroll 4
    for (int j = 0; j < TILE_H; j++) {
        float4 c4 = *(const float4*)(src + (size_t)j * Hdim);
        const float fv = fs[j], ik = iks[j], qv = qs[j];
        float4 cn;
        cn.x = fmaf(fv, c4.x, ik * v4.x);
        cn.y = fmaf(fv, c4.y, ik * v4.y);
        cn.z = fmaf(fv, c4.z, ik * v4.z);
        cn.w = fmaf(fv, c4.w, ik * v4.w);
        *(float4*)(dst + (size_t)j * Hdim) = cn;
        acc.x = fmaf(qv, cn.x, acc.x);
        acc.y = fmaf(qv, cn.y, acc.y);
        acc.z = fmaf(qv, cn.z, acc.z);
        acc.w = fmaf(qv, cn.w, acc.w);
    }

    *(float4*)(g_hpart + ((ht * Bsz + b) << 10) + d) = acc;
}

// ---------------------------------------------------------------------------
// K4: h_new = o * (h_lin0 + h_lin1) / denom
// ---------------------------------------------------------------------------
__global__ __launch_bounds__(256) void finalize_h_kernel(float* __restrict__ out_h)
{
    const int idx = blockIdx.x * 256 + threadIdx.x;   // 131072 total
    const int b = idx >> 10;
    const int d = idx & 1023;
    float hl = g_hpart[(b << 10) + d] + g_hpart[(Bsz << 10) + (b << 10) + d];
    out_h[idx] = g_ifo[b * NQKV + 2048 + d] * hl / g_denom[b];
}

// ---------------------------------------------------------------------------
extern "C" void kernel_launch(void* const* d_in, const int* in_sizes, int n_in,
                              void* d_out, int out_size)
{
    // ---- order-agnostic input resolution by element count ----
    const float *x = 0, *C = 0, *n_in_p = 0;
    const float *W_proj = 0, *b_proj = 0, *W_gates = 0, *b_gates = 0;

    const float* trio[3] = {0, 0, 0};
    int ntrio = 0;
    for (int idx = 0; idx < n_in; idx++) {
        const float* p = (const float*)d_in[idx];
        switch (in_sizes[idx]) {
            case 134217728: C       = p; break;
            case 4194304:   W_proj  = p; break;
            case 3145728:   W_gates = p; break;
            case 4096:      b_proj  = p; break;
            case 3072:      b_gates = p; break;
            case 131072:    if (ntrio < 3) trio[ntrio++] = p; break;
            default: break;
        }
    }
    n_in_p = trio[1];                       // n is middle in both plausible orders
    if (in_sizes[0] == 131072) x = trio[0]; // insertion order: x first
    else                       x = trio[2]; // alphabetical: x last

    float* out   = (float*)d_out;
    float* out_h = out;                                    // 128*1024
    float* out_C = out + Bsz * Hdim;                       // 128*1024*1024
    float* out_n = out + Bsz * Hdim + (size_t)Bsz * Hdim * Hdim;

    dim3 ggrid(NQKV / 64, Bsz / 64);
    // K1: proj GEMM (q,k tanh; v identity; g skipped) -> g_qkv
    gemm_act_kernel<0><<<ggrid, 128>>>(x, W_proj, b_proj);
    // K2: gates GEMM (sigmoid), A = v slice of g_qkv (resolved in-device) -> g_ifo
    gemm_act_kernel<1><<<ggrid, 128>>>(nullptr, W_gates, b_gates);
    // K2b: n_new + denom
    nnew_denom_kernel<<<Bsz, 256>>>(n_in_p, out_n);
    // K3: C update + fused h_lin reduction
    update_C_kernel<<<Bsz * 4, 128>>>(C, out_C);
    // K4: finalize h
    finalize_h_kernel<<<(Bsz * Hdim) / 256, 256>>>(out_h);
}

// round 4
// speedup vs baseline: 1.2010x; 1.2010x over previous
#include <cuda_runtime.h>
#include <math.h>

// ---------------------------------------------------------------------------
// mLSTM cell, B=128, D_IN=1024, H=1024
// output: concat[ h_new (128*1024), C_new (128*1024*1024), n_new (128*1024) ]
// ---------------------------------------------------------------------------

#define Bsz   128
#define Hdim  1024
#define NQKV  3072   // dead 'g' quarter of proj is skipped
#define KSPLIT 8
#define OUTMN (Bsz * NQKV)   // 393216

__device__ float g_qkv[Bsz * NQKV];        // [b][ q | k | v ]
__device__ float g_ifo[Bsz * NQKV];        // [b][ i | f | o ]
__device__ float g_part[KSPLIT * OUTMN];   // split-K partials (reused K1/K2)
__device__ float g_hpart[8 * Bsz * Hdim];  // per-h-tile h_lin partials
__device__ float g_denom[Bsz];

// ---------------------------------------------------------------------------
// Split-K GEMM mainloop: partial[kz] += A[128, k-chunk] * W[k-chunk, 3072]
// MODE 0: A = x (arg, lda=1024), W ld=4096 ; MODE 1: A = v slice of g_qkv
// BM=64 BN=64 BK=16, 256 threads, 4x4 per-thread tile, K chunk = 128.
// grid (48, 2, KSPLIT)
// ---------------------------------------------------------------------------
template <int MODE>
__global__ __launch_bounds__(256) void gemm_main_kernel(
    const float* __restrict__ Aext, const float* __restrict__ W)
{
    constexpr int BM = 64, BN = 64, BK = 16;
    const float* __restrict__ A = (MODE == 0) ? Aext : (const float*)(g_qkv + 2048);
    const int lda = (MODE == 0) ? 1024 : NQKV;
    const int ldw = (MODE == 0) ? 4096 : 3072;

    __shared__ float As[BK][BM + 4];   // transposed; +4 keeps 16B alignment
    __shared__ float Ws[BK][BN];

    const int tid = threadIdx.x;
    const int bm = blockIdx.y * BM;
    const int bn = blockIdx.x * BN;
    const int kz = blockIdx.z;

    const int aRow = tid >> 2;          // 0..63
    const int aK4  = (tid & 3) * 4;
    const int wRow = tid >> 4;          // 0..15
    const int wN4  = (tid & 15) * 4;

    const int trow = (tid >> 4) * 4;    // 0..60
    const int tcol = (tid & 15) * 4;    // 0..60

    float acc[4][4];
#pragma unroll
    for (int r = 0; r < 4; r++)
#pragma unroll
        for (int c = 0; c < 4; c++) acc[r][c] = 0.f;

    const int kbeg = kz * (1024 / KSPLIT);
    const int kend = kbeg + (1024 / KSPLIT);

    for (int k0 = kbeg; k0 < kend; k0 += BK) {
        float4 av = *(const float4*)(A + (size_t)(bm + aRow) * lda + k0 + aK4);
        As[aK4 + 0][aRow] = av.x;
        As[aK4 + 1][aRow] = av.y;
        As[aK4 + 2][aRow] = av.z;
        As[aK4 + 3][aRow] = av.w;
        *(float4*)&Ws[wRow][wN4] =
            *(const float4*)(W + (size_t)(k0 + wRow) * ldw + bn + wN4);
        __syncthreads();

#pragma unroll
        for (int kk = 0; kk < BK; kk++) {
            float4 a4 = *(const float4*)&As[kk][trow];
            float4 w4 = *(const float4*)&Ws[kk][tcol];
            float a[4] = {a4.x, a4.y, a4.z, a4.w};
            float w[4] = {w4.x, w4.y, w4.z, w4.w};
#pragma unroll
            for (int r = 0; r < 4; r++)
#pragma unroll
                for (int c = 0; c < 4; c++)
                    acc[r][c] = fmaf(a[r], w[c], acc[r][c]);
        }
        __syncthreads();
    }

    float* __restrict__ part = g_part + (size_t)kz * OUTMN;
#pragma unroll
    for (int r = 0; r < 4; r++) {
        int m = bm + trow + r;
        float4 o4 = make_float4(acc[r][0], acc[r][1], acc[r][2], acc[r][3]);
        *(float4*)(part + (size_t)m * NQKV + bn + tcol) = o4;
    }
}

// ---------------------------------------------------------------------------
// GEMM epilogue: sum KSPLIT partials + bias + activation -> g_qkv / g_ifo
// MODE 0: tanh for n<2048, identity for v ; MODE 1: sigmoid
// ---------------------------------------------------------------------------
template <int MODE>
__global__ __launch_bounds__(256) void gemm_epi_kernel(const float* __restrict__ bias)
{
    const int idx = blockIdx.x * 256 + threadIdx.x;   // 0 .. OUTMN-1
    const int nn = idx % NQKV;
    float v = bias[nn];
#pragma unroll
    for (int p = 0; p < KSPLIT; p++) v += g_part[(size_t)p * OUTMN + idx];
    if (MODE == 0) {
        if (nn < 2048) v = tanhf(v);
        g_qkv[idx] = v;
    } else {
        g_ifo[idx] = 1.0f / (1.0f + expf(-v));
    }
}

// ---------------------------------------------------------------------------
// n_new = f*n + i*k ; denom[b] = max(sum_d q*n_new, 1e-6)
// ---------------------------------------------------------------------------
__global__ __launch_bounds__(256) void nnew_denom_kernel(
    const float* __restrict__ n_in, float* __restrict__ out_n)
{
    const int b = blockIdx.x;
    const int tid = threadIdx.x;
    __shared__ float red[256];

    float psum = 0.f;
#pragma unroll
    for (int d = tid; d < Hdim; d += 256) {
        float iv = g_ifo[b * NQKV + d];
        float fv = g_ifo[b * NQKV + 1024 + d];
        float kv = g_qkv[b * NQKV + 1024 + d];
        float qv = g_qkv[b * NQKV + d];
        float nn = fv * n_in[b * Hdim + d] + iv * kv;
        out_n[b * Hdim + d] = nn;
        psum += qv * nn;
    }
    red[tid] = psum;
    __syncthreads();
#pragma unroll
    for (int s = 128; s > 0; s >>= 1) {
        if (tid < s) red[tid] += red[tid + s];
        __syncthreads();
    }
    if (tid == 0) g_denom[b] = fmaxf(red[0], 1e-6f);
}

// ---------------------------------------------------------------------------
// K3: streaming C update fused with h_lin reduction (single pass over C).
// grid = 128 b * 8 htiles = 1024 blocks, 256 threads (full 1024-wide d row).
// ---------------------------------------------------------------------------
#define TILE_H 128

__global__ __launch_bounds__(256) void update_C_kernel(
    const float* __restrict__ C, float* __restrict__ outC)
{
    const int bid = blockIdx.x;
    const int b  = bid >> 3;
    const int ht = bid & 7;
    const int tid = threadIdx.x;

    __shared__ float qs[TILE_H], fs[TILE_H], iks[TILE_H];
    if (tid < TILE_H) {
        int h = ht * TILE_H + tid;
        qs[tid]  = g_qkv[b * NQKV + h];
        float kv = g_qkv[b * NQKV + 1024 + h];
        float iv = g_ifo[b * NQKV + h];
        fs[tid]  = g_ifo[b * NQKV + 1024 + h];
        iks[tid] = iv * kv;
    }
    __syncthreads();

    const int d = tid * 4;
    const float4 v4 = *(const float4*)(g_qkv + b * NQKV + 2048 + d);

    const size_t base = (size_t)b * Hdim * Hdim + (size_t)ht * TILE_H * Hdim + d;
    const float* __restrict__ src = C + base;
    float* __restrict__ dst = outC + base;

    float4 acc = make_float4(0.f, 0.f, 0.f, 0.f);

#pragma unroll 8
    for (int j = 0; j < TILE_H; j++) {
        float4 c4 = __ldcs((const float4*)(src + (size_t)j * Hdim));
        const float fv = fs[j], ik = iks[j], qv = qs[j];
        float4 cn;
        cn.x = fmaf(fv, c4.x, ik * v4.x);
        cn.y = fmaf(fv, c4.y, ik * v4.y);
        cn.z = fmaf(fv, c4.z, ik * v4.z);
        cn.w = fmaf(fv, c4.w, ik * v4.w);
        __stcs((float4*)(dst + (size_t)j * Hdim), cn);
        acc.x = fmaf(qv, cn.x, acc.x);
        acc.y = fmaf(qv, cn.y, acc.y);
        acc.z = fmaf(qv, cn.z, acc.z);
        acc.w = fmaf(qv, cn.w, acc.w);
    }

    *(float4*)(g_hpart + ht * (Bsz * Hdim) + (b << 10) + d) = acc;
}

// ---------------------------------------------------------------------------
// K4: h_new = o * (sum_ht h_lin_part) / denom
// ---------------------------------------------------------------------------
__global__ __launch_bounds__(256) void finalize_h_kernel(float* __restrict__ out_h)
{
    const int idx = blockIdx.x * 256 + threadIdx.x;   // 131072 total
    const int b = idx >> 10;
    const int d = idx & 1023;
    float hl = 0.f;
#pragma unroll
    for (int p = 0; p < 8; p++) hl += g_hpart[p * (Bsz * Hdim) + (b << 10) + d];
    out_h[idx] = g_ifo[b * NQKV + 2048 + d] * hl / g_denom[b];
}

// ---------------------------------------------------------------------------
extern "C" void kernel_launch(void* const* d_in, const int* in_sizes, int n_in,
                              void* d_out, int out_size)
{
    // order-agnostic input resolution by element count
    const float *x = 0, *C = 0, *n_in_p = 0;
    const float *W_proj = 0, *b_proj = 0, *W_gates = 0, *b_gates = 0;

    const float* trio[3] = {0, 0, 0};
    int ntrio = 0;
    for (int idx = 0; idx < n_in; idx++) {
        const float* p = (const float*)d_in[idx];
        switch (in_sizes[idx]) {
            case 134217728: C       = p; break;
            case 4194304:   W_proj  = p; break;
            case 3145728:   W_gates = p; break;
            case 4096:      b_proj  = p; break;
            case 3072:      b_gates = p; break;
            case 131072:    if (ntrio < 3) trio[ntrio++] = p; break;
            default: break;
        }
    }
    n_in_p = trio[1];
    if (in_sizes[0] == 131072) x = trio[0];
    else                       x = trio[2];

    float* out   = (float*)d_out;
    float* out_h = out;
    float* out_C = out + Bsz * Hdim;
    float* out_n = out + Bsz * Hdim + (size_t)Bsz * Hdim * Hdim;

    dim3 ggrid(NQKV / 64, Bsz / 64, KSPLIT);
    // K1: proj GEMM -> partials -> epi(tanh/identity) -> g_qkv
    gemm_main_kernel<0><<<ggrid, 256>>>(x, W_proj);
    gemm_epi_kernel<0><<<OUTMN / 256, 256>>>(b_proj);
    // K2: gates GEMM (A = v slice, resolved in-device) -> epi(sigmoid) -> g_ifo
    gemm_main_kernel<1><<<ggrid, 256>>>(nullptr, W_gates);
    gemm_epi_kernel<1><<<OUTMN / 256, 256>>>(b_gates);
    // n_new + denom
    nnew_denom_kernel<<<Bsz, 256>>>(n_in_p, out_n);
    // C update + fused h_lin reduction (single pass over C)
    update_C_kernel<<<Bsz * 8, 256>>>(C, out_C);
    // finalize h
    finalize_h_kernel<<<(Bsz * Hdim) / 256, 256>>>(out_h);
}

// round 6
// speedup vs baseline: 1.4556x; 1.2120x over previous
#include <cuda_runtime.h>
#include <math.h>

// ---------------------------------------------------------------------------
// mLSTM cell, B=128, D_IN=1024, H=1024  (SIMT only: harness ptxas targets
// sm_103 without the 'a' feature set, so tcgen05 is unavailable)
// output: concat[ h_new (128*1024), C_new (128*1024*1024), n_new (128*1024) ]
// ---------------------------------------------------------------------------

#define Bsz   128
#define Hdim  1024
#define NQKV  3072   // dead 'g' quarter of proj is skipped
#define KSPLIT 3
#define OUTMN (Bsz * NQKV)   // 393216

__device__ float g_qkv[Bsz * NQKV];        // [b][ q | k | v ]
__device__ float g_ifo[Bsz * NQKV];        // [b][ i | f | o ]
__device__ float g_part[KSPLIT * OUTMN];   // split-K partials (reused K1/K2)
__device__ float g_hpart[8 * Bsz * Hdim];  // per-h-tile h_lin partials
__device__ float g_denom[Bsz];

// ---------------------------------------------------------------------------
// Split-K GEMM mainloop: partial[kz] = A[128, k-chunk] * W[k-chunk, 3072]
// MODE 0: A = x (arg, lda=1024), ldw = 4096 ; MODE 1: A = v slice of g_qkv
// BM=64 BN=64 BK=16, 128 threads, 8x4 per-thread tile, double-buffered smem.
// grid (48, 2, 3); K split as 22/21/21 BK-iterations.
// ---------------------------------------------------------------------------
template <int MODE>
__global__ __launch_bounds__(128) void gemm_main_kernel(
    const float* __restrict__ Aext, const float* __restrict__ W)
{
    const float* __restrict__ A = (MODE == 0) ? Aext : (const float*)(g_qkv + 2048);
    const int lda = (MODE == 0) ? 1024 : NQKV;
    const int ldw = (MODE == 0) ? 4096 : 3072;

    __shared__ float As[2][16][72];   // [buf][kk][m], 72 keeps 16B alignment
    __shared__ float Bs[2][16][64];

    const int tid = threadIdx.x;
    const int bm = blockIdx.y * 64;
    const int bn = blockIdx.x * 64;
    const int kz = blockIdx.z;

    // A loads: 64 rows x 16 k. Thread t: row = t>>1, k base = (t&1)*8 (2 float4)
    const int aRow = tid >> 1;
    const int aK   = (tid & 1) * 8;
    // B loads: 16 rows(k) x 64 cols = 256 float4; g = tid, tid+128
    const int bRow0 = tid >> 4;          // 0..7
    const int bCol  = (tid & 15) * 4;

    // compute mapping: ty 0..7 -> 8 M rows (ty*8..+7), tx 0..15 -> 4 N cols
    const int ty = tid >> 4;
    const int tx = tid & 15;
    const int mrow = ty * 8;
    const int ncol = tx * 4;

    float acc[8][4];
#pragma unroll
    for (int r = 0; r < 8; r++)
#pragma unroll
        for (int c = 0; c < 4; c++) acc[r][c] = 0.f;

    const int it0   = kz * 21 + (kz > 0 ? 1 : 0);   // 0, 22, 43
    const int iters = (kz == 0) ? 22 : 21;

    // ---- prefetch first tile into buffer 0 ----
    {
        const int k0 = it0 * 16;
        float4 av0 = *(const float4*)(A + (size_t)(bm + aRow) * lda + k0 + aK);
        float4 av1 = *(const float4*)(A + (size_t)(bm + aRow) * lda + k0 + aK + 4);
        As[0][aK + 0][aRow] = av0.x; As[0][aK + 1][aRow] = av0.y;
        As[0][aK + 2][aRow] = av0.z; As[0][aK + 3][aRow] = av0.w;
        As[0][aK + 4][aRow] = av1.x; As[0][aK + 5][aRow] = av1.y;
        As[0][aK + 6][aRow] = av1.z; As[0][aK + 7][aRow] = av1.w;
        float4 bv0 = *(const float4*)(W + (size_t)(k0 + bRow0) * ldw + bn + bCol);
        float4 bv1 = *(const float4*)(W + (size_t)(k0 + bRow0 + 8) * ldw + bn + bCol);
        *(float4*)&Bs[0][bRow0][bCol]     = bv0;
        *(float4*)&Bs[0][bRow0 + 8][bCol] = bv1;
    }
    __syncthreads();

    int cur = 0;
    for (int it = 0; it < iters; it++) {
        const bool has = (it + 1 < iters);
        float4 av0, av1, bv0, bv1;
        if (has) {
            const int k0 = (it0 + it + 1) * 16;
            av0 = *(const float4*)(A + (size_t)(bm + aRow) * lda + k0 + aK);
            av1 = *(const float4*)(A + (size_t)(bm + aRow) * lda + k0 + aK + 4);
            bv0 = *(const float4*)(W + (size_t)(k0 + bRow0) * ldw + bn + bCol);
            bv1 = *(const float4*)(W + (size_t)(k0 + bRow0 + 8) * ldw + bn + bCol);
        }

#pragma unroll
        for (int kk = 0; kk < 16; kk++) {
            float4 a0 = *(const float4*)&As[cur][kk][mrow];
            float4 a1 = *(const float4*)&As[cur][kk][mrow + 4];
            float4 b4 = *(const float4*)&Bs[cur][kk][ncol];
            float a[8] = {a0.x, a0.y, a0.z, a0.w, a1.x, a1.y, a1.z, a1.w};
            float b[4] = {b4.x, b4.y, b4.z, b4.w};
#pragma unroll
            for (int r = 0; r < 8; r++)
#pragma unroll
                for (int c = 0; c < 4; c++)
                    acc[r][c] = fmaf(a[r], b[c], acc[r][c]);
        }

        if (has) {
            const int nxt = cur ^ 1;
            As[nxt][aK + 0][aRow] = av0.x; As[nxt][aK + 1][aRow] = av0.y;
            As[nxt][aK + 2][aRow] = av0.z; As[nxt][aK + 3][aRow] = av0.w;
            As[nxt][aK + 4][aRow] = av1.x; As[nxt][aK + 5][aRow] = av1.y;
            As[nxt][aK + 6][aRow] = av1.z; As[nxt][aK + 7][aRow] = av1.w;
            *(float4*)&Bs[nxt][bRow0][bCol]     = bv0;
            *(float4*)&Bs[nxt][bRow0 + 8][bCol] = bv1;
            __syncthreads();
            cur = nxt;
        }
    }

    float* __restrict__ part = g_part + (size_t)kz * OUTMN;
#pragma unroll
    for (int r = 0; r < 8; r++) {
        int m = bm + mrow + r;
        float4 o4 = make_float4(acc[r][0], acc[r][1], acc[r][2], acc[r][3]);
        *(float4*)(part + (size_t)m * NQKV + bn + ncol) = o4;
    }
}

// ---------------------------------------------------------------------------
// GEMM epilogue: sum KSPLIT partials + bias + activation -> g_qkv / g_ifo
// MODE 0: tanh for n<2048, identity for v ; MODE 1: sigmoid
// ---------------------------------------------------------------------------
template <int MODE>
__global__ __launch_bounds__(256) void gemm_epi_kernel(const float* __restrict__ bias)
{
    const int idx = blockIdx.x * 256 + threadIdx.x;   // 0 .. OUTMN-1
    const int nn = idx % NQKV;
    float v = bias[nn];
#pragma unroll
    for (int p = 0; p < KSPLIT; p++) v += g_part[(size_t)p * OUTMN + idx];
    if (MODE == 0) {
        if (nn < 2048) v = tanhf(v);
        g_qkv[idx] = v;
    } else {
        g_ifo[idx] = 1.0f / (1.0f + expf(-v));
    }
}

// ---------------------------------------------------------------------------
// n_new = f*n + i*k ; denom[b] = max(sum_d q*n_new, 1e-6)
// ---------------------------------------------------------------------------
__global__ __launch_bounds__(256) void nnew_denom_kernel(
    const float* __restrict__ n_in, float* __restrict__ out_n)
{
    const int b = blockIdx.x;
    const int tid = threadIdx.x;
    __shared__ float red[256];

    float psum = 0.f;
#pragma unroll
    for (int d = tid; d < Hdim; d += 256) {
        float iv = g_ifo[b * NQKV + d];
        float fv = g_ifo[b * NQKV + 1024 + d];
        float kv = g_qkv[b * NQKV + 1024 + d];
        float qv = g_qkv[b * NQKV + d];
        float nn = fv * n_in[b * Hdim + d] + iv * kv;
        out_n[b * Hdim + d] = nn;
        psum += qv * nn;
    }
    red[tid] = psum;
    __syncthreads();
#pragma unroll
    for (int s = 128; s > 0; s >>= 1) {
        if (tid < s) red[tid] += red[tid + s];
        __syncthreads();
    }
    if (tid == 0) g_denom[b] = fmaxf(red[0], 1e-6f);
}

// ---------------------------------------------------------------------------
// K3: streaming C update fused with h_lin reduction (single pass over C).
// grid = 128 b * 8 htiles = 1024 blocks, 256 threads (full 1024-wide d row).
// ---------------------------------------------------------------------------
#define TILE_H 128

__global__ __launch_bounds__(256) void update_C_kernel(
    const float* __restrict__ C, float* __restrict__ outC)
{
    const int bid = blockIdx.x;
    const int b  = bid >> 3;
    const int ht = bid & 7;
    const int tid = threadIdx.x;

    __shared__ float qs[TILE_H], fs[TILE_H], iks[TILE_H];
    if (tid < TILE_H) {
        int h = ht * TILE_H + tid;
        qs[tid]  = g_qkv[b * NQKV + h];
        float kv = g_qkv[b * NQKV + 1024 + h];
        float iv = g_ifo[b * NQKV + h];
        fs[tid]  = g_ifo[b * NQKV + 1024 + h];
        iks[tid] = iv * kv;
    }
    __syncthreads();

    const int d = tid * 4;
    const float4 v4 = *(const float4*)(g_qkv + b * NQKV + 2048 + d);

    const size_t base = (size_t)b * Hdim * Hdim + (size_t)ht * TILE_H * Hdim + d;
    const float* __restrict__ src = C + base;
    float* __restrict__ dst = outC + base;

    float4 acc = make_float4(0.f, 0.f, 0.f, 0.f);

#pragma unroll 8
    for (int j = 0; j < TILE_H; j++) {
        float4 c4 = __ldcs((const float4*)(src + (size_t)j * Hdim));
        const float fv = fs[j], ik = iks[j], qv = qs[j];
        float4 cn;
        cn.x = fmaf(fv, c4.x, ik * v4.x);
        cn.y = fmaf(fv, c4.y, ik * v4.y);
        cn.z = fmaf(fv, c4.z, ik * v4.z);
        cn.w = fmaf(fv, c4.w, ik * v4.w);
        __stcs((float4*)(dst + (size_t)j * Hdim), cn);
        acc.x = fmaf(qv, cn.x, acc.x);
        acc.y = fmaf(qv, cn.y, acc.y);
        acc.z = fmaf(qv, cn.z, acc.z);
        acc.w = fmaf(qv, cn.w, acc.w);
    }

    *(float4*)(g_hpart + ht * (Bsz * Hdim) + (b << 10) + d) = acc;
}

// ---------------------------------------------------------------------------
// K4: h_new = o * (sum_ht h_lin_part) / denom
// ---------------------------------------------------------------------------
__global__ __launch_bounds__(256) void finalize_h_kernel(float* __restrict__ out_h)
{
    const int idx = blockIdx.x * 256 + threadIdx.x;   // 131072 total
    const int b = idx >> 10;
    const int d = idx & 1023;
    float hl = 0.f;
#pragma unroll
    for (int p = 0; p < 8; p++) hl += g_hpart[p * (Bsz * Hdim) + (b << 10) + d];
    out_h[idx] = g_ifo[b * NQKV + 2048 + d] * hl / g_denom[b];
}

// ---------------------------------------------------------------------------
extern "C" void kernel_launch(void* const* d_in, const int* in_sizes, int n_in,
                              void* d_out, int out_size)
{
    // order-agnostic input resolution by element count
    const float *x = 0, *C = 0, *n_in_p = 0;
    const float *W_proj = 0, *b_proj = 0, *W_gates = 0, *b_gates = 0;

    const float* trio[3] = {0, 0, 0};
    int ntrio = 0;
    for (int idx = 0; idx < n_in; idx++) {
        const float* p = (const float*)d_in[idx];
        switch (in_sizes[idx]) {
            case 134217728: C       = p; break;
            case 4194304:   W_proj  = p; break;
            case 3145728:   W_gates = p; break;
            case 4096:      b_proj  = p; break;
            case 3072:      b_gates = p; break;
            case 131072:    if (ntrio < 3) trio[ntrio++] = p; break;
            default: break;
        }
    }
    n_in_p = trio[1];
    if (in_sizes[0] == 131072) x = trio[0];
    else                       x = trio[2];

    float* out   = (float*)d_out;
    float* out_h = out;
    float* out_C = out + Bsz * Hdim;
    float* out_n = out + Bsz * Hdim + (size_t)Bsz * Hdim * Hdim;

    dim3 ggrid(NQKV / 64, Bsz / 64, KSPLIT);   // (48, 2, 3) = 288 blocks
    // K1: proj GEMM -> partials -> epi(tanh/identity) -> g_qkv
    gemm_main_kernel<0><<<ggrid, 128>>>(x, W_proj);
    gemm_epi_kernel<0><<<OUTMN / 256, 256>>>(b_proj);
    // K2: gates GEMM (A = v slice, resolved in-device) -> epi(sigmoid) -> g_ifo
    gemm_main_kernel<1><<<ggrid, 128>>>(nullptr, W_gates);
    gemm_epi_kernel<1><<<OUTMN / 256, 256>>>(b_gates);
    // n_new + denom
    nnew_denom_kernel<<<Bsz, 256>>>(n_in_p, out_n);
    // C update + fused h_lin reduction (single pass over C)
    update_C_kernel<<<Bsz * 8, 256>>>(C, out_C);
    // finalize h
    finalize_h_kernel<<<(Bsz * Hdim) / 256, 256>>>(out_h);
}